// round 7
// baseline (speedup 1.0000x reference)
#include <cuda_runtime.h>
#include <cuda_bf16.h>
#include <math.h>
#include <cstdint>

// ---------------------------------------------------------------------------
// SSMXLSTMFusion: D=512, S=3, BATCH=256, H=8, HD=64
// Round 7: Taylor chain in 3 iterations (4+8+8 terms) using A^1..A^8;
// extra powers co-launched with chain iter 1; DAG-level task co-scheduling;
// fused small kernels; attn consumes split-K partials directly.
// ---------------------------------------------------------------------------

#define DD    512
#define BB    256
#define SS    3

// ------------------------- scratch (device globals) ------------------------
__device__ float g_h1   [BB*DD];
__device__ float g_delta[BB];
__device__ float g_bx   [BB*DD];
__device__ float g_T    [BB*DD];
__device__ float g_U    [2*BB*8*DD];          // 2 split-K planes of [256,4096]
__device__ float g_AT   [DD*DD];
__device__ float g_A2T  [DD*DD];
__device__ float g_A4T  [DD*DD];
__device__ float g_AoT  [DD*DD];
__device__ float g_M    [DD*DD];
__device__ float g_Wpow [8*DD*DD];            // A^1..A^8
__device__ float g_gA   [SS*BB*4*DD];
__device__ float g_gB   [SS*BB*4*DD];
__device__ float g_kvp  [2*SS*BB*2*DD];
__device__ float g_qp   [2*BB*DD];
__device__ float g_ctx  [BB*DD];
__device__ float g_part [10*BB*DD];
__device__ float g_pvec [DD];

// ========================= task descriptor ==================================
struct GTask {
    const float *X, *W, *Wn2, *bias;
    float *C, *Cn2, *Ct;
    int ldX, ldW, ldC, ldCn2, ldCt;
    int K, kofs, nsplit, mtiles, blocks;
};
struct GTaskSet { GTask t[12]; int ntasks; };

#define NOSPLIT (1<<30)

// ========================= smem layout ======================================
#define RSB   80
#define PLANE (128*RSB)
#define OFF_AHI 0
#define OFF_ALO (PLANE)
#define OFF_BHI (2*PLANE)
#define OFF_BLO (3*PLANE)

__device__ __forceinline__ uint32_t smem_to_u32(const void* p) {
    uint32_t a;
    asm("{ .reg .u64 t; cvta.to.shared.u64 t, %1; cvt.u32.u64 %0, t; }"
        : "=r"(a) : "l"(p));
    return a;
}

__device__ __forceinline__ uint32_t pkbf(float a, float b) {
    __nv_bfloat16 h0 = __float2bfloat16_rn(a);
    __nv_bfloat16 h1 = __float2bfloat16_rn(b);
    uint16_t u0 = *(uint16_t*)&h0, u1 = *(uint16_t*)&h1;
    return (uint32_t)u0 | ((uint32_t)u1 << 16);
}

__device__ __forceinline__ void split8(float4 u, float4 v, uint4& hi, uint4& lo)
{
    float f[8] = {u.x,u.y,u.z,u.w,v.x,v.y,v.z,v.w};
    float r[8];
    uint32_t h[4];
    #pragma unroll
    for (int i = 0; i < 4; i++) {
        __nv_bfloat16 b0 = __float2bfloat16_rn(f[2*i]);
        __nv_bfloat16 b1 = __float2bfloat16_rn(f[2*i+1]);
        r[2*i]   = f[2*i]   - __bfloat162float(b0);
        r[2*i+1] = f[2*i+1] - __bfloat162float(b1);
        uint16_t u0 = *(uint16_t*)&b0, u1 = *(uint16_t*)&b1;
        h[i] = (uint32_t)u0 | ((uint32_t)u1 << 16);
    }
    hi = make_uint4(h[0], h[1], h[2], h[3]);
    lo = make_uint4(pkbf(r[0],r[1]), pkbf(r[2],r[3]),
                    pkbf(r[4],r[5]), pkbf(r[6],r[7]));
}

__device__ __forceinline__ void ldm_x4(uint32_t* r, uint32_t addr) {
    asm volatile("ldmatrix.sync.aligned.m8n8.x4.shared.b16 {%0,%1,%2,%3}, [%4];"
        : "=r"(r[0]), "=r"(r[1]), "=r"(r[2]), "=r"(r[3]) : "r"(addr));
}

__device__ __forceinline__ void mma_bf16(float* c, const uint32_t* a, const uint32_t* b)
{
    asm volatile(
        "mma.sync.aligned.m16n8k16.row.col.f32.bf16.bf16.f32 "
        "{%0,%1,%2,%3}, {%4,%5,%6,%7}, {%8,%9}, {%0,%1,%2,%3};"
        : "+f"(c[0]), "+f"(c[1]), "+f"(c[2]), "+f"(c[3])
        : "r"(a[0]), "r"(a[1]), "r"(a[2]), "r"(a[3]), "r"(b[0]), "r"(b[1]));
}

__device__ __forceinline__ void prefetch_op(const GTask& T, bool isA,
    int lrow0, int lcb, int m0, int n0, int k0, float4* pf)
{
    if (isA) {
        const float* base = T.X + (long)(m0 + lrow0) * T.ldX + k0 + lcb;
        #pragma unroll
        for (int j = 0; j < 4; j++) {
            const float* src = base + (long)(j*32) * T.ldX;
            pf[2*j]   = *(const float4*)(src);
            pf[2*j+1] = *(const float4*)(src + 4);
        }
    } else {
        #pragma unroll
        for (int j = 0; j < 4; j++) {
            int ng = n0 + j*32 + lrow0;
            const float* row = (ng >= T.nsplit)
                ? T.Wn2 + (long)(ng - T.nsplit) * T.ldW
                : T.W   + (long)ng * T.ldW;
            const float* src = row + k0 + lcb;
            pf[2*j]   = *(const float4*)(src);
            pf[2*j+1] = *(const float4*)(src + 4);
        }
    }
}

// ========================= GEMM kernel ======================================
__global__ void __launch_bounds__(256, 1)
gemm_mma(GTaskSet ts)
{
    __shared__ char smem[4*PLANE];

    int b = blockIdx.x, ti = 0;
    while (b >= ts.t[ti].blocks) { b -= ts.t[ti].blocks; ti++; }
    const GTask T = ts.t[ti];
    const int m0 = (b % T.mtiles) * 128;
    const int n0 = (b / T.mtiles) * 128;

    const int tid = threadIdx.x;
    const int lid = tid & 31;
    const int wid = tid >> 5;
    const int m_base = (wid & 3) * 32;
    const int n_base = (wid >> 2) * 64;
    const int gid = lid >> 2;
    const int tig = lid & 3;
    const int g  = lid >> 3;
    const int ig = lid & 7;

    const uint32_t sm = smem_to_u32(smem);
    const uint32_t a_ad = sm + (uint32_t)((m_base + (g&1)*8 + ig) * RSB + (g>>1)*16);
    const uint32_t b_ad = sm + (uint32_t)((n_base + (g>>1)*8 + ig) * RSB + (g&1)*16);

    float acc[2][8][4];
    #pragma unroll
    for (int i = 0; i < 2; i++)
        #pragma unroll
        for (int j = 0; j < 8; j++)
            #pragma unroll
            for (int k = 0; k < 4; k++) acc[i][j][k] = 0.0f;

    const int lr = tid & 127;
    const bool isA = tid < 128;
    const int lrow0 = lr >> 2;
    const int lcb   = (lr & 3) * 8;

    const int nc = T.K >> 5;
    float4 pf[8];
    prefetch_op(T, isA, lrow0, lcb, m0, n0, T.kofs, pf);

    char* ph = smem + (isA ? OFF_AHI : OFF_BHI) + lrow0 * RSB + lcb * 2;
    char* pl = smem + (isA ? OFF_ALO : OFF_BLO) + lrow0 * RSB + lcb * 2;

    for (int c = 0; c < nc; c++) {
        __syncthreads();
        #pragma unroll
        for (int j = 0; j < 4; j++) {
            uint4 hi, lo;
            split8(pf[2*j], pf[2*j+1], hi, lo);
            *(uint4*)(ph + j*32*RSB) = hi;
            *(uint4*)(pl + j*32*RSB) = lo;
        }
        __syncthreads();
        if (c + 1 < nc)
            prefetch_op(T, isA, lrow0, lcb, m0, n0, T.kofs + (c+1)*32, pf);

        #pragma unroll
        for (int ks = 0; ks < 2; ks++) {
            const uint32_t kb = ks * 32;
            uint32_t ahi[2][4], alo[2][4], bhi[8][2], blo[8][2];
            #pragma unroll
            for (int mt = 0; mt < 2; mt++) {
                ldm_x4(ahi[mt], a_ad + OFF_AHI + mt*16*RSB + kb);
                ldm_x4(alo[mt], a_ad + OFF_ALO + mt*16*RSB + kb);
            }
            #pragma unroll
            for (int np = 0; np < 4; np++) {
                uint32_t r[4];
                ldm_x4(r, b_ad + OFF_BHI + np*16*RSB + kb);
                bhi[2*np][0] = r[0]; bhi[2*np][1] = r[1];
                bhi[2*np+1][0] = r[2]; bhi[2*np+1][1] = r[3];
                ldm_x4(r, b_ad + OFF_BLO + np*16*RSB + kb);
                blo[2*np][0] = r[0]; blo[2*np][1] = r[1];
                blo[2*np+1][0] = r[2]; blo[2*np+1][1] = r[3];
            }
            #pragma unroll
            for (int mt = 0; mt < 2; mt++)
                #pragma unroll
                for (int nt = 0; nt < 8; nt++) {
                    mma_bf16(acc[mt][nt], ahi[mt], bhi[nt]);
                    mma_bf16(acc[mt][nt], ahi[mt], blo[nt]);
                    mma_bf16(acc[mt][nt], alo[mt], bhi[nt]);
                }
        }
    }

    #pragma unroll
    for (int mt = 0; mt < 2; mt++) {
        #pragma unroll
        for (int nt = 0; nt < 8; nt++) {
            int n = n0 + n_base + nt*8 + tig*2;
            #pragma unroll
            for (int half = 0; half < 2; half++) {
                int mm = m0 + m_base + mt*16 + gid + half*8;
                float v0 = acc[mt][nt][half*2];
                float v1 = acc[mt][nt][half*2 + 1];
                if (T.Cn2 && n >= T.nsplit) {
                    int nn = n - T.nsplit;
                    *(float2*)(T.Cn2 + (long)mm*T.ldCn2 + nn) = make_float2(v0, v1);
                } else {
                    if (T.bias) { v0 += T.bias[n]; v1 += T.bias[n+1]; }
                    *(float2*)(T.C + (long)mm*T.ldC + n) = make_float2(v0, v1);
                    if (T.Ct) {
                        T.Ct[(long)n*T.ldCt + mm]     = v0;
                        T.Ct[(long)(n+1)*T.ldCt + mm] = v1;
                    }
                }
            }
        }
    }
}

// ========================= small SIMT kernels ===============================
__global__ void transpose2_kernel(const float* __restrict__ A,
                                  float* __restrict__ AT,
                                  float* __restrict__ W0,
                                  const float* __restrict__ B,
                                  float* __restrict__ BT)
{
    __shared__ float t[32][33];
    const float* src = blockIdx.z ? B : A;
    float* dst = blockIdx.z ? BT : AT;
    int bx = blockIdx.x*32, by = blockIdx.y*32;
    int x = bx + threadIdx.x;
    #pragma unroll
    for (int i = 0; i < 32; i += 8) {
        int y = by + threadIdx.y + i;
        float v = src[(long)y*DD + x];
        t[threadIdx.y + i][threadIdx.x] = v;
        if (blockIdx.z == 0) W0[(long)y*DD + x] = v;
    }
    __syncthreads();
    int xo = by + threadIdx.x;
    #pragma unroll
    for (int i = 0; i < 32; i += 8) {
        int yo = bx + threadIdx.y + i;
        dst[(long)yo*DD + xo] = t[threadIdx.x][threadIdx.y + i];
    }
}

__device__ __forceinline__ float sigf(float x) { return 1.0f / (1.0f + expf(-x)); }

// fused S1: blocks [0,256) delta; [256,768) pvec; [768,2304) lstm pointwise
__global__ void s1_kernel(const float* __restrict__ h1,
                          const float* __restrict__ dn_g,
                          const float* __restrict__ dn_beta,
                          const float* __restrict__ w2,
                          const float* __restrict__ b2,
                          float* __restrict__ delta,
                          const float* __restrict__ proj_w,
                          const float* __restrict__ aob,
                          const float* __restrict__ proj_b,
                          float* __restrict__ pvec,
                          const float* __restrict__ gA,
                          const float* __restrict__ gB,
                          const float* __restrict__ bih,
                          const float* __restrict__ bhh,
                          const float* __restrict__ lstm_c,
                          const float* __restrict__ decays,
                          float* __restrict__ h_new,
                          float* __restrict__ c_new)
{
    int blk = blockIdx.x, t = threadIdx.x;
    if (blk < 256) {
        // ---- delta: LN + gelu + dot + softplus ----
        __shared__ float red[256];
        int row = blk;
        const float* r = h1 + (long)row * DD;
        float x0 = r[t], x1 = r[t + 256];
        red[t] = x0 + x1; __syncthreads();
        for (int o = 128; o > 0; o >>= 1) { if (t < o) red[t] += red[t+o]; __syncthreads(); }
        float mean = red[0] * (1.0f/DD);
        __syncthreads();
        float d0 = x0 - mean, d1 = x1 - mean;
        red[t] = d0*d0 + d1*d1; __syncthreads();
        for (int o = 128; o > 0; o >>= 1) { if (t < o) red[t] += red[t+o]; __syncthreads(); }
        float inv = rsqrtf(red[0] * (1.0f/DD) + 1e-5f);
        __syncthreads();
        float y0 = d0 * inv * dn_g[t]     + dn_beta[t];
        float y1 = d1 * inv * dn_g[t+256] + dn_beta[t+256];
        y0 = 0.5f * y0 * (1.0f + erff(y0 * 0.70710678118654752f));
        y1 = 0.5f * y1 * (1.0f + erff(y1 * 0.70710678118654752f));
        red[t] = y0*w2[t] + y1*w2[t+256]; __syncthreads();
        for (int o = 128; o > 0; o >>= 1) { if (t < o) red[t] += red[t+o]; __syncthreads(); }
        if (t == 0) {
            float z = red[0] + b2[0];
            delta[row] = (z > 20.0f) ? z : log1pf(expf(z));
        }
    } else if (blk < 768) {
        // ---- pvec ----
        __shared__ float red[256];
        int row = blk - 256;
        const float* r = proj_w + (long)row * 2560 + 512;
        red[t] = r[t]*aob[t] + r[t+256]*aob[t+256];
        __syncthreads();
        for (int o = 128; o > 0; o >>= 1) { if (t < o) red[t] += red[t+o]; __syncthreads(); }
        if (t == 0) pvec[row] = proj_b[row] + red[0];
    } else {
        // ---- lstm pointwise ----
        int idx = (blk - 768) * 256 + t;
        int s = idx / (BB*DD);
        int r = idx - s * (BB*DD);
        int b = r >> 9;
        int d = r & 511;
        long gbase = ((long)s * BB + b) * 2048;
        const float* a = gA + gbase;
        const float* h = gB + gbase;
        const float* bi = bih + s*2048;
        const float* bh = bhh + s*2048;
        float ip = a[d]      + h[d]      + bi[d]      + bh[d];
        float fp = a[512+d]  + h[512+d]  + bi[512+d]  + bh[512+d];
        float gp = a[1024+d] + h[1024+d] + bi[1024+d] + bh[1024+d];
        float op = a[1536+d] + h[1536+d] + bi[1536+d] + bh[1536+d];
        float i_g = sigf(ip);
        float f_g = sigf(fp);
        float g_g = tanhf(gp);
        float o_g = sigf(op);
        float c   = lstm_c[idx];
        float craw = f_g * c + i_g * g_g;
        float hn   = o_g * tanhf(craw);
        float dec  = decays[s];
        h_new[idx] = hn;
        c_new[idx] = dec * c + (1.0f - dec) * craw;
    }
}

// chain epilogue: U has 2 split-K planes (stride PB), row stride nt*512.
__global__ void chain_epilogue_kernel(const float* __restrict__ U,
                                      const float* __restrict__ delta,
                                      float* __restrict__ T,
                                      float* __restrict__ y,
                                      const float* __restrict__ h_prev,
                                      int k0, int nt,
                                      const float* __restrict__ bx,
                                      int last)
{
    int idx = blockIdx.x * blockDim.x + threadIdx.x;
    if (idx >= BB*DD) return;
    int b = idx >> 9, n = idx & 511;
    const long PB = (long)BB * 4096;
    const float* u0 = U + (long)b * (nt*512) + n;
    float d  = delta[b];
    float c  = 1.0f;
    float yy = (k0 == 0) ? h_prev[idx] : y[idx];
    float tl = 0.0f;
    for (int j = 0; j < nt; j++) {
        float u = u0[j*512] + u0[PB + j*512];
        c *= d / (float)(k0 + j + 1);
        tl = c * u;
        yy += tl;
    }
    if (last) yy += d * bx[idx];
    y[idx] = yy;
    T[idx] = tl;
}

// attention; consumes kv and q split-K partials + biases directly
__global__ void attn_kernel(const float* __restrict__ qp,
                            const float* __restrict__ kvp,
                            const float* __restrict__ attn_in_b,
                            float* __restrict__ ctx)
{
    int b    = blockIdx.x;
    int warp = threadIdx.x >> 5;
    int lane = threadIdx.x & 31;
    const long QP = (long)BB*DD;
    const long KP = (long)SS*BB*2*DD;

    long qo = (long)b * DD + warp * 64;
    float q0 = qp[qo + lane]      + qp[QP + qo + lane]      + attn_in_b[warp*64 + lane];
    float q1 = qp[qo + lane + 32] + qp[QP + qo + lane + 32] + attn_in_b[warp*64 + lane + 32];

    float sc[SS];
    #pragma unroll
    for (int s = 0; s < SS; s++) {
        long ko = (long)(s*BB + b) * 1024 + warp * 64;
        float k0 = kvp[ko + lane]      + kvp[KP + ko + lane]
                 + attn_in_b[512 + warp*64 + lane];
        float k1 = kvp[ko + lane + 32] + kvp[KP + ko + lane + 32]
                 + attn_in_b[512 + warp*64 + lane + 32];
        float d = q0 * k0 + q1 * k1;
        #pragma unroll
        for (int o = 16; o > 0; o >>= 1) d += __shfl_xor_sync(0xffffffff, d, o);
        sc[s] = d * 0.125f;
    }
    float m = fmaxf(sc[0], fmaxf(sc[1], sc[2]));
    float e[SS], sum = 0.0f;
    #pragma unroll
    for (int s = 0; s < SS; s++) { e[s] = expf(sc[s] - m); sum += e[s]; }
    float inv = 1.0f / sum;

    float c0 = 0.0f, c1 = 0.0f;
    #pragma unroll
    for (int s = 0; s < SS; s++) {
        long vo = (long)(s*BB + b) * 1024 + 512 + warp * 64;
        float v0 = kvp[vo + lane]      + kvp[KP + vo + lane]
                 + attn_in_b[1024 + warp*64 + lane];
        float v1 = kvp[vo + lane + 32] + kvp[KP + vo + lane + 32]
                 + attn_in_b[1024 + warp*64 + lane + 32];
        float w = e[s] * inv;
        c0 += w * v0;
        c1 += w * v1;
    }
    ctx[(long)b * DD + warp*64 + lane]      = c0;
    ctx[(long)b * DD + warp*64 + lane + 32] = c1;
}

// sum 10 proj partial planes + pvec -> layernorm -> out
__global__ void proj_ln_kernel(const float* __restrict__ part,
                               const float* __restrict__ pvec,
                               const float* __restrict__ g,
                               const float* __restrict__ be,
                               float* __restrict__ out)
{
    __shared__ float red[256];
    int row = blockIdx.x, t = threadIdx.x;
    long o0 = (long)row*DD + t, o1 = o0 + 256;
    const long PL = (long)BB*DD;
    float x0 = pvec[t], x1 = pvec[t+256];
    #pragma unroll
    for (int p = 0; p < 10; p++) { x0 += part[p*PL + o0]; x1 += part[p*PL + o1]; }

    red[t] = x0 + x1; __syncthreads();
    for (int o = 128; o > 0; o >>= 1) { if (t < o) red[t] += red[t+o]; __syncthreads(); }
    float mean = red[0] * (1.0f/DD);
    __syncthreads();

    float d0 = x0 - mean, d1 = x1 - mean;
    red[t] = d0*d0 + d1*d1; __syncthreads();
    for (int o = 128; o > 0; o >>= 1) { if (t < o) red[t] += red[t+o]; __syncthreads(); }
    float inv = rsqrtf(red[0] * (1.0f/DD) + 1e-5f);

    out[o0] = d0 * inv * g[t]     + be[t];
    out[o1] = d1 * inv * g[t+256] + be[t+256];
}

// ---------------------------------------------------------------------------
static inline GTask mk_task(const float* X, int ldX, const float* W, int ldW,
                            float* C, int ldC, int K, int kofs,
                            int mtiles, int ntiles)
{
    GTask t = {};
    t.X = X; t.ldX = ldX; t.W = W; t.ldW = ldW; t.C = C; t.ldC = ldC;
    t.K = K; t.kofs = kofs; t.nsplit = NOSPLIT;
    t.mtiles = mtiles; t.blocks = mtiles*ntiles;
    return t;
}

extern "C" void kernel_launch(void* const* d_in, const int* in_sizes, int n_in,
                              void* d_out, int out_size)
{
    (void)in_sizes; (void)n_in; (void)out_size;

    const float* x        = (const float*)d_in[0];
    const float* h_prev   = (const float*)d_in[1];
    const float* lstm_h   = (const float*)d_in[2];
    const float* lstm_c   = (const float*)d_in[3];
    const float* A        = (const float*)d_in[4];
    const float* Bm       = (const float*)d_in[5];
    const float* dn_w1    = (const float*)d_in[6];
    const float* dn_b1    = (const float*)d_in[7];
    const float* dn_g     = (const float*)d_in[8];
    const float* dn_beta  = (const float*)d_in[9];
    const float* dn_w2    = (const float*)d_in[10];
    const float* dn_b2    = (const float*)d_in[11];
    const float* lstm_wih = (const float*)d_in[12];
    const float* lstm_whh = (const float*)d_in[13];
    const float* lstm_bih = (const float*)d_in[14];
    const float* lstm_bhh = (const float*)d_in[15];
    const float* decays   = (const float*)d_in[16];
    const float* attn_in_w  = (const float*)d_in[17];
    const float* attn_in_b  = (const float*)d_in[18];
    const float* attn_out_w = (const float*)d_in[19];
    const float* attn_out_b = (const float*)d_in[20];
    const float* proj_w   = (const float*)d_in[21];
    const float* proj_b   = (const float*)d_in[22];
    const float* proj_g   = (const float*)d_in[23];
    const float* proj_beta= (const float*)d_in[24];

    float* out = (float*)d_out;
    float* out_y    = out;
    float* out_hssm = out + BB*DD;
    float* out_hnew = out + 2*BB*DD;
    float* out_cnew = out + 2*BB*DD + SS*BB*DD;

    float *p_h1, *p_delta, *p_bx, *p_T, *p_U, *p_AT, *p_A2T, *p_A4T, *p_AoT,
          *p_M, *p_Wpow, *p_gA, *p_gB, *p_kvp, *p_qp, *p_ctx, *p_part, *p_pvec;
    cudaGetSymbolAddress((void**)&p_h1,    g_h1);
    cudaGetSymbolAddress((void**)&p_delta, g_delta);
    cudaGetSymbolAddress((void**)&p_bx,    g_bx);
    cudaGetSymbolAddress((void**)&p_T,     g_T);
    cudaGetSymbolAddress((void**)&p_U,     g_U);
    cudaGetSymbolAddress((void**)&p_AT,    g_AT);
    cudaGetSymbolAddress((void**)&p_A2T,   g_A2T);
    cudaGetSymbolAddress((void**)&p_A4T,   g_A4T);
    cudaGetSymbolAddress((void**)&p_AoT,   g_AoT);
    cudaGetSymbolAddress((void**)&p_M,     g_M);
    cudaGetSymbolAddress((void**)&p_Wpow,  g_Wpow);
    cudaGetSymbolAddress((void**)&p_gA,    g_gA);
    cudaGetSymbolAddress((void**)&p_gB,    g_gB);
    cudaGetSymbolAddress((void**)&p_kvp,   g_kvp);
    cudaGetSymbolAddress((void**)&p_qp,    g_qp);
    cudaGetSymbolAddress((void**)&p_ctx,   g_ctx);
    cudaGetSymbolAddress((void**)&p_part,  g_part);
    cudaGetSymbolAddress((void**)&p_pvec,  g_pvec);

    const long W2 = (long)DD*DD;

    // ---- T0: AT = A^T (+Wpow0 = A), AoT = attn_out_w^T ----
    transpose2_kernel<<<dim3(16,16,2), dim3(32,8)>>>(A, p_AT, p_Wpow,
                                                     attn_out_w, p_AoT);

    // ---- G1 (240 blocks): h1|bx, 6 lstm partials, A^2 (+A2T), M ----
    {
        GTaskSet ts = {};
        GTask t0 = mk_task(x, DD, dn_w1, DD, p_h1, DD, DD, 0, 2, 8);
        t0.bias = dn_b1; t0.Wn2 = Bm; t0.Cn2 = p_bx; t0.ldCn2 = DD; t0.nsplit = DD;
        ts.t[0] = t0;
        for (int s = 0; s < SS; s++) {
            ts.t[1+s] = mk_task(x, DD, lstm_wih + (long)s*4*W2, DD,
                                p_gA + (long)s*BB*4*DD, 4*DD, DD, 0, 2, 16);
            ts.t[4+s] = mk_task(lstm_h + (long)s*BB*DD, DD,
                                lstm_whh + (long)s*4*W2, DD,
                                p_gB + (long)s*BB*4*DD, 4*DD, DD, 0, 2, 16);
        }
        GTask ta = mk_task(A, DD, p_AT, DD, p_Wpow + W2, DD, DD, 0, 4, 4);
        ta.Ct = p_A2T; ta.ldCt = DD;
        ts.t[7] = ta;
        ts.t[8] = mk_task(proj_w + 512, 5*DD, p_AoT, DD, p_M, DD, DD, 0, 4, 4);
        ts.ntasks = 9;
        gemm_mma<<<240, 256>>>(ts);
    }

    // ---- S1 fused: delta, pvec, lstm pointwise ----
    s1_kernel<<<2304, 256>>>(p_h1, dn_g, dn_beta, dn_w2, dn_b2, p_delta,
                             proj_w, attn_out_b, proj_b, p_pvec,
                             p_gA, p_gB, lstm_bih, lstm_bhh, lstm_c, decays,
                             out_hnew, out_cnew);

    // ---- G2 (128 blocks): A^3, A^4 (+A4T), kv split-K-2 ----
    {
        GTaskSet ts = {};
        ts.t[0] = mk_task(p_Wpow + W2, DD, p_AT, DD, p_Wpow + 2*W2, DD, DD, 0, 4, 4);
        GTask t4 = mk_task(p_Wpow + W2, DD, p_A2T, DD, p_Wpow + 3*W2, DD, DD, 0, 4, 4);
        t4.Ct = p_A4T; t4.ldCt = DD;
        ts.t[1] = t4;
        for (int kz = 0; kz < 2; kz++)
            ts.t[2+kz] = mk_task(out_hnew, DD, attn_in_w + W2, DD,
                                 p_kvp + (long)kz*SS*BB*2*DD, 2*DD, 256, kz*256, 6, 8);
        ts.ntasks = 4;
        gemm_mma<<<128, 256>>>(ts);
    }

    // ---- GC1 (176 blocks): chain iter1 (4 terms, split-K-2),
    //      A^5..A^8, h_new proj partials (planes 4..9) ----
    {
        GTaskSet ts = {};
        for (int kz = 0; kz < 2; kz++)
            ts.t[kz] = mk_task(h_prev, DD, p_Wpow, DD,
                               p_U + (long)kz*BB*4096, 4*DD, 256, kz*256, 2, 16);
        ts.t[2] = mk_task(p_Wpow + 3*W2, DD, p_AT,  DD, p_Wpow + 4*W2, DD, DD, 0, 4, 4);
        ts.t[3] = mk_task(p_Wpow + 3*W2, DD, p_A2T, DD, p_Wpow + 5*W2, DD, DD, 0, 4, 4);
        ts.t[4] = mk_task(p_Wpow + 2*W2, DD, p_A4T, DD, p_Wpow + 6*W2, DD, DD, 0, 4, 4);
        ts.t[5] = mk_task(p_Wpow + 3*W2, DD, p_A4T, DD, p_Wpow + 7*W2, DD, DD, 0, 4, 4);
        int p = 6;
        for (int i = 0; i < SS; i++)
            for (int kz = 0; kz < 2; kz++, p++)
                ts.t[p] = mk_task(out_hnew + (long)i*BB*DD, DD,
                                  proj_w + 1024 + i*512, 5*DD,
                                  p_part + (long)(4 + (p-6))*BB*DD, DD,
                                  256, kz*256, 2, 4);
        ts.ntasks = 12;
        gemm_mma<<<176, 256>>>(ts);
    }
    chain_epilogue_kernel<<<(BB*DD)/256, 256>>>(
        p_U, p_delta, p_T, out_hssm, h_prev, 0, 4, p_bx, 0);

    // ---- chain iters 2,3: 8 terms each, split-K-2 (128 blocks) ----
    for (int it = 0; it < 2; it++) {
        GTaskSet ts = {};
        for (int kz = 0; kz < 2; kz++)
            ts.t[kz] = mk_task(p_T, DD, p_Wpow, DD,
                               p_U + (long)kz*BB*4096, 8*DD, 256, kz*256, 2, 32);
        ts.ntasks = 2;
        gemm_mma<<<128, 256>>>(ts);
        chain_epilogue_kernel<<<(BB*DD)/256, 256>>>(
            p_U, p_delta, p_T, out_hssm, h_prev, 4 + 8*it, 8, p_bx, it == 1);
    }

    // ---- G4 (32 blocks): q split-K-2 + hssm proj (planes 0,1) ----
    {
        GTaskSet ts = {};
        for (int kz = 0; kz < 2; kz++) {
            ts.t[kz] = mk_task(out_hssm, DD, attn_in_w, DD,
                               p_qp + (long)kz*BB*DD, DD, 256, kz*256, 2, 4);
            ts.t[2+kz] = mk_task(out_hssm, DD, proj_w, 5*DD,
                                 p_part + (long)kz*BB*DD, DD, 256, kz*256, 2, 4);
        }
        ts.ntasks = 4;
        gemm_mma<<<32, 256>>>(ts);
    }

    // ---- attention (consumes partials + bias) ----
    attn_kernel<<<BB, 256>>>(p_qp, p_kvp, attn_in_b, p_ctx);

    // ---- G5 (16 blocks): ctx @ M^T -> planes 2,3 ----
    {
        GTaskSet ts = {};
        for (int kz = 0; kz < 2; kz++)
            ts.t[kz] = mk_task(p_ctx, DD, p_M, DD,
                               p_part + (long)(2+kz)*BB*DD, DD, 256, kz*256, 2, 4);
        ts.ntasks = 2;
        gemm_mma<<<16, 256>>>(ts);
    }

    // ---- reduce + LN -> out_y ----
    proj_ln_kernel<<<BB, 256>>>(p_part, p_pvec, proj_g, proj_beta, out_y);
}

// round 8
// speedup vs baseline: 1.1617x; 1.1617x over previous
#include <cuda_runtime.h>
#include <cuda_bf16.h>
#include <math.h>
#include <cstdint>

// ---------------------------------------------------------------------------
// SSMXLSTMFusion: D=512, S=3, BATCH=256, H=8, HD=64
// Round 8: 128x64 block tiles / 2 CTAs per SM (occupancy was the binder),
// Taylor chain 2 iterations of 8 terms (A^1..A^8, KT=16), split-K only
// where needed. bf16 hi/lo emulated fp32 mma.sync.
// ---------------------------------------------------------------------------

#define DD    512
#define BB    256
#define SS    3

// ------------------------- scratch (device globals) ------------------------
__device__ float g_h1   [BB*DD];
__device__ float g_delta[BB];
__device__ float g_bx   [BB*DD];
__device__ float g_T    [BB*DD];
__device__ float g_U    [BB*8*DD];            // [256, 4096] single plane
__device__ float g_AT   [DD*DD];
__device__ float g_A2T  [DD*DD];
__device__ float g_A4T  [DD*DD];
__device__ float g_AoT  [DD*DD];
__device__ float g_M    [DD*DD];
__device__ float g_Wpow [8*DD*DD];            // A^1..A^8
__device__ float g_gA   [SS*BB*4*DD];
__device__ float g_gB   [SS*BB*4*DD];
__device__ float g_kvp  [2*SS*BB*2*DD];
__device__ float g_qp   [2*BB*DD];
__device__ float g_ctx  [BB*DD];
__device__ float g_part [10*BB*DD];
__device__ float g_pvec [DD];

// ========================= task descriptor ==================================
struct GTask {
    const float *X, *W, *Wn2, *bias;
    float *C, *Cn2, *Ct;
    int ldX, ldW, ldC, ldCn2, ldCt;
    int K, kofs, nsplit, mtiles, blocks;
};
struct GTaskSet { GTask t[12]; int ntasks; };

#define NOSPLIT (1<<30)

// ========================= smem layout ======================================
// A planes: 128 rows, B planes: 64 rows; RSB = 80 bytes (32 bf16 + pad)
#define RSB     80
#define OFF_AHI 0
#define OFF_ALO 10240
#define OFF_BHI 20480
#define OFF_BLO 25600
#define SMEM_SZ 30720

__device__ __forceinline__ uint32_t smem_to_u32(const void* p) {
    uint32_t a;
    asm("{ .reg .u64 t; cvta.to.shared.u64 t, %1; cvt.u32.u64 %0, t; }"
        : "=r"(a) : "l"(p));
    return a;
}

__device__ __forceinline__ uint32_t pkbf(float a, float b) {
    __nv_bfloat16 h0 = __float2bfloat16_rn(a);
    __nv_bfloat16 h1 = __float2bfloat16_rn(b);
    uint16_t u0 = *(uint16_t*)&h0, u1 = *(uint16_t*)&h1;
    return (uint32_t)u0 | ((uint32_t)u1 << 16);
}

__device__ __forceinline__ void split8(float4 u, float4 v, uint4& hi, uint4& lo)
{
    float f[8] = {u.x,u.y,u.z,u.w,v.x,v.y,v.z,v.w};
    float r[8];
    uint32_t h[4];
    #pragma unroll
    for (int i = 0; i < 4; i++) {
        __nv_bfloat16 b0 = __float2bfloat16_rn(f[2*i]);
        __nv_bfloat16 b1 = __float2bfloat16_rn(f[2*i+1]);
        r[2*i]   = f[2*i]   - __bfloat162float(b0);
        r[2*i+1] = f[2*i+1] - __bfloat162float(b1);
        uint16_t u0 = *(uint16_t*)&b0, u1 = *(uint16_t*)&b1;
        h[i] = (uint32_t)u0 | ((uint32_t)u1 << 16);
    }
    hi = make_uint4(h[0], h[1], h[2], h[3]);
    lo = make_uint4(pkbf(r[0],r[1]), pkbf(r[2],r[3]),
                    pkbf(r[4],r[5]), pkbf(r[6],r[7]));
}

__device__ __forceinline__ void ldm_x4(uint32_t* r, uint32_t addr) {
    asm volatile("ldmatrix.sync.aligned.m8n8.x4.shared.b16 {%0,%1,%2,%3}, [%4];"
        : "=r"(r[0]), "=r"(r[1]), "=r"(r[2]), "=r"(r[3]) : "r"(addr));
}

__device__ __forceinline__ void mma_bf16(float* c, const uint32_t* a, const uint32_t* b)
{
    asm volatile(
        "mma.sync.aligned.m16n8k16.row.col.f32.bf16.bf16.f32 "
        "{%0,%1,%2,%3}, {%4,%5,%6,%7}, {%8,%9}, {%0,%1,%2,%3};"
        : "+f"(c[0]), "+f"(c[1]), "+f"(c[2]), "+f"(c[3])
        : "r"(a[0]), "r"(a[1]), "r"(a[2]), "r"(a[3]), "r"(b[0]), "r"(b[1]));
}

// ========================= GEMM kernel ======================================
// Block tile 128(M) x 64(N); 256 threads = 8 warps (4m x 2n), warp tile 32x32.
// K in 32-wide chunks, register-prefetched. 2 CTAs per SM.
__global__ void __launch_bounds__(256, 2)
gemm_mma(GTaskSet ts)
{
    __shared__ char smem[SMEM_SZ];

    int b = blockIdx.x, ti = 0;
    while (b >= ts.t[ti].blocks) { b -= ts.t[ti].blocks; ti++; }
    const GTask T = ts.t[ti];
    const int m0 = (b % T.mtiles) * 128;
    const int n0 = (b / T.mtiles) * 64;

    const int tid = threadIdx.x;
    const int lid = tid & 31;
    const int wid = tid >> 5;
    const int m_base = (wid & 3) * 32;
    const int n_base = (wid >> 2) * 32;
    const int gid = lid >> 2;
    const int tig = lid & 3;
    const int g  = lid >> 3;
    const int ig = lid & 7;

    const uint32_t sm = smem_to_u32(smem);
    const uint32_t a_ad = sm + (uint32_t)((m_base + (g&1)*8 + ig) * RSB + (g>>1)*16);
    const uint32_t b_ad = sm + (uint32_t)((n_base + (g>>1)*8 + ig) * RSB + (g&1)*16);

    float acc[2][4][4];
    #pragma unroll
    for (int i = 0; i < 2; i++)
        #pragma unroll
        for (int j = 0; j < 4; j++)
            #pragma unroll
            for (int k = 0; k < 4; k++) acc[i][j][k] = 0.0f;

    // loaders: every thread does 2 A slices + 1 B slice per chunk.
    // A: unit u = tid (+256): row=u>>2 in [0,128), slice=u&3
    // B: unit tid: row=tid>>2 in [0,64), slice=tid&3
    const int rowA = tid >> 2;          // A rows rowA and rowA+64
    const int sl   = tid & 3;           // slice (8 floats)
    const int rowB = tid >> 2 >= 64 ? (tid >> 2) - 64 : (tid >> 2); // 0..63 (dup ok)
    // B loader: use tid>>2 mod 64
    const int rB = (tid >> 2) & 63;

    const int nc = T.K >> 5;
    float4 pfA[4], pfB[2];
    {
        const float* a0 = T.X + (long)(m0 + rowA) * T.ldX + T.kofs + sl*8;
        pfA[0] = ((const float4*)a0)[0]; pfA[1] = ((const float4*)a0)[1];
        const float* a1 = a0 + (long)64 * T.ldX;
        pfA[2] = ((const float4*)a1)[0]; pfA[3] = ((const float4*)a1)[1];
        int ng = n0 + rB;
        const float* br = (ng >= T.nsplit)
            ? T.Wn2 + (long)(ng - T.nsplit) * T.ldW
            : T.W   + (long)ng * T.ldW;
        const float* b0 = br + T.kofs + sl*8;
        pfB[0] = ((const float4*)b0)[0]; pfB[1] = ((const float4*)b0)[1];
    }
    (void)rowB;

    char* phA = smem + OFF_AHI + rowA * RSB + sl * 16;
    char* plA = smem + OFF_ALO + rowA * RSB + sl * 16;
    char* phB = smem + OFF_BHI + rB * RSB + sl * 16;
    char* plB = smem + OFF_BLO + rB * RSB + sl * 16;
    const bool doB = (tid >> 2) < 64;   // first 256 units cover B once

    for (int c = 0; c < nc; c++) {
        __syncthreads();
        {
            uint4 hi, lo;
            split8(pfA[0], pfA[1], hi, lo);
            *(uint4*)(phA) = hi; *(uint4*)(plA) = lo;
            split8(pfA[2], pfA[3], hi, lo);
            *(uint4*)(phA + 64*RSB) = hi; *(uint4*)(plA + 64*RSB) = lo;
            if (doB) {
                split8(pfB[0], pfB[1], hi, lo);
                *(uint4*)(phB) = hi; *(uint4*)(plB) = lo;
            }
        }
        __syncthreads();
        if (c + 1 < nc) {
            int k0 = T.kofs + (c+1)*32;
            const float* a0 = T.X + (long)(m0 + rowA) * T.ldX + k0 + sl*8;
            pfA[0] = ((const float4*)a0)[0]; pfA[1] = ((const float4*)a0)[1];
            const float* a1 = a0 + (long)64 * T.ldX;
            pfA[2] = ((const float4*)a1)[0]; pfA[3] = ((const float4*)a1)[1];
            int ng = n0 + rB;
            const float* br = (ng >= T.nsplit)
                ? T.Wn2 + (long)(ng - T.nsplit) * T.ldW
                : T.W   + (long)ng * T.ldW;
            const float* b0 = br + k0 + sl*8;
            pfB[0] = ((const float4*)b0)[0]; pfB[1] = ((const float4*)b0)[1];
        }

        #pragma unroll
        for (int ks = 0; ks < 2; ks++) {
            const uint32_t kb = ks * 32;
            uint32_t ahi[2][4], alo[2][4], bhi[4][2], blo[4][2];
            #pragma unroll
            for (int mt = 0; mt < 2; mt++) {
                ldm_x4(ahi[mt], a_ad + OFF_AHI + mt*16*RSB + kb);
                ldm_x4(alo[mt], a_ad + OFF_ALO + mt*16*RSB + kb);
            }
            #pragma unroll
            for (int np = 0; np < 2; np++) {
                uint32_t r[4];
                ldm_x4(r, b_ad + OFF_BHI + np*16*RSB + kb);
                bhi[2*np][0] = r[0]; bhi[2*np][1] = r[1];
                bhi[2*np+1][0] = r[2]; bhi[2*np+1][1] = r[3];
                ldm_x4(r, b_ad + OFF_BLO + np*16*RSB + kb);
                blo[2*np][0] = r[0]; blo[2*np][1] = r[1];
                blo[2*np+1][0] = r[2]; blo[2*np+1][1] = r[3];
            }
            #pragma unroll
            for (int mt = 0; mt < 2; mt++)
                #pragma unroll
                for (int nt = 0; nt < 4; nt++) {
                    mma_bf16(acc[mt][nt], ahi[mt], bhi[nt]);
                    mma_bf16(acc[mt][nt], ahi[mt], blo[nt]);
                    mma_bf16(acc[mt][nt], alo[mt], bhi[nt]);
                }
        }
    }

    #pragma unroll
    for (int mt = 0; mt < 2; mt++) {
        #pragma unroll
        for (int nt = 0; nt < 4; nt++) {
            int n = n0 + n_base + nt*8 + tig*2;
            #pragma unroll
            for (int half = 0; half < 2; half++) {
                int mm = m0 + m_base + mt*16 + gid + half*8;
                float v0 = acc[mt][nt][half*2];
                float v1 = acc[mt][nt][half*2 + 1];
                if (T.Cn2 && n >= T.nsplit) {
                    int nn = n - T.nsplit;
                    *(float2*)(T.Cn2 + (long)mm*T.ldCn2 + nn) = make_float2(v0, v1);
                } else {
                    if (T.bias) { v0 += T.bias[n]; v1 += T.bias[n+1]; }
                    *(float2*)(T.C + (long)mm*T.ldC + n) = make_float2(v0, v1);
                    if (T.Ct) {
                        T.Ct[(long)n*T.ldCt + mm]     = v0;
                        T.Ct[(long)(n+1)*T.ldCt + mm] = v1;
                    }
                }
            }
        }
    }
}

// ========================= small SIMT kernels ===============================
__global__ void transpose2_kernel(const float* __restrict__ A,
                                  float* __restrict__ AT,
                                  float* __restrict__ W0,
                                  const float* __restrict__ B,
                                  float* __restrict__ BT)
{
    __shared__ float t[32][33];
    const float* src = blockIdx.z ? B : A;
    float* dst = blockIdx.z ? BT : AT;
    int bx = blockIdx.x*32, by = blockIdx.y*32;
    int x = bx + threadIdx.x;
    #pragma unroll
    for (int i = 0; i < 32; i += 8) {
        int y = by + threadIdx.y + i;
        float v = src[(long)y*DD + x];
        t[threadIdx.y + i][threadIdx.x] = v;
        if (blockIdx.z == 0) W0[(long)y*DD + x] = v;
    }
    __syncthreads();
    int xo = by + threadIdx.x;
    #pragma unroll
    for (int i = 0; i < 32; i += 8) {
        int yo = bx + threadIdx.y + i;
        dst[(long)yo*DD + xo] = t[threadIdx.x][threadIdx.y + i];
    }
}

__device__ __forceinline__ float sigf(float x) { return 1.0f / (1.0f + expf(-x)); }

// fused S1: blocks [0,256) delta; [256,768) pvec; [768,2304) lstm pointwise
__global__ void s1_kernel(const float* __restrict__ h1,
                          const float* __restrict__ dn_g,
                          const float* __restrict__ dn_beta,
                          const float* __restrict__ w2,
                          const float* __restrict__ b2,
                          float* __restrict__ delta,
                          const float* __restrict__ proj_w,
                          const float* __restrict__ aob,
                          const float* __restrict__ proj_b,
                          float* __restrict__ pvec,
                          const float* __restrict__ gA,
                          const float* __restrict__ gB,
                          const float* __restrict__ bih,
                          const float* __restrict__ bhh,
                          const float* __restrict__ lstm_c,
                          const float* __restrict__ decays,
                          float* __restrict__ h_new,
                          float* __restrict__ c_new)
{
    int blk = blockIdx.x, t = threadIdx.x;
    if (blk < 256) {
        __shared__ float red[256];
        int row = blk;
        const float* r = h1 + (long)row * DD;
        float x0 = r[t], x1 = r[t + 256];
        red[t] = x0 + x1; __syncthreads();
        for (int o = 128; o > 0; o >>= 1) { if (t < o) red[t] += red[t+o]; __syncthreads(); }
        float mean = red[0] * (1.0f/DD);
        __syncthreads();
        float d0 = x0 - mean, d1 = x1 - mean;
        red[t] = d0*d0 + d1*d1; __syncthreads();
        for (int o = 128; o > 0; o >>= 1) { if (t < o) red[t] += red[t+o]; __syncthreads(); }
        float inv = rsqrtf(red[0] * (1.0f/DD) + 1e-5f);
        __syncthreads();
        float y0 = d0 * inv * dn_g[t]     + dn_beta[t];
        float y1 = d1 * inv * dn_g[t+256] + dn_beta[t+256];
        y0 = 0.5f * y0 * (1.0f + erff(y0 * 0.70710678118654752f));
        y1 = 0.5f * y1 * (1.0f + erff(y1 * 0.70710678118654752f));
        red[t] = y0*w2[t] + y1*w2[t+256]; __syncthreads();
        for (int o = 128; o > 0; o >>= 1) { if (t < o) red[t] += red[t+o]; __syncthreads(); }
        if (t == 0) {
            float z = red[0] + b2[0];
            delta[row] = (z > 20.0f) ? z : log1pf(expf(z));
        }
    } else if (blk < 768) {
        __shared__ float red[256];
        int row = blk - 256;
        const float* r = proj_w + (long)row * 2560 + 512;
        red[t] = r[t]*aob[t] + r[t+256]*aob[t+256];
        __syncthreads();
        for (int o = 128; o > 0; o >>= 1) { if (t < o) red[t] += red[t+o]; __syncthreads(); }
        if (t == 0) pvec[row] = proj_b[row] + red[0];
    } else {
        int idx = (blk - 768) * 256 + t;
        int s = idx / (BB*DD);
        int r = idx - s * (BB*DD);
        int b = r >> 9;
        int d = r & 511;
        long gbase = ((long)s * BB + b) * 2048;
        const float* a = gA + gbase;
        const float* h = gB + gbase;
        const float* bi = bih + s*2048;
        const float* bh = bhh + s*2048;
        float ip = a[d]      + h[d]      + bi[d]      + bh[d];
        float fp = a[512+d]  + h[512+d]  + bi[512+d]  + bh[512+d];
        float gp = a[1024+d] + h[1024+d] + bi[1024+d] + bh[1024+d];
        float op = a[1536+d] + h[1536+d] + bi[1536+d] + bh[1536+d];
        float i_g = sigf(ip);
        float f_g = sigf(fp);
        float g_g = tanhf(gp);
        float o_g = sigf(op);
        float c   = lstm_c[idx];
        float craw = f_g * c + i_g * g_g;
        float hn   = o_g * tanhf(craw);
        float dec  = decays[s];
        h_new[idx] = hn;
        c_new[idx] = dec * c + (1.0f - dec) * craw;
    }
}

// chain epilogue: U single plane [256, nt*512]
__global__ void chain_epilogue_kernel(const float* __restrict__ U,
                                      const float* __restrict__ delta,
                                      float* __restrict__ T,
                                      float* __restrict__ y,
                                      const float* __restrict__ h_prev,
                                      int k0, int nt,
                                      const float* __restrict__ bx,
                                      int last)
{
    int idx = blockIdx.x * blockDim.x + threadIdx.x;
    if (idx >= BB*DD) return;
    int b = idx >> 9, n = idx & 511;
    const float* u0 = U + (long)b * (nt*512) + n;
    float d  = delta[b];
    float c  = 1.0f;
    float yy = (k0 == 0) ? h_prev[idx] : y[idx];
    float tl = 0.0f;
    for (int j = 0; j < nt; j++) {
        float u = u0[j*512];
        c *= d / (float)(k0 + j + 1);
        tl = c * u;
        yy += tl;
    }
    if (last) yy += d * bx[idx];
    y[idx] = yy;
    T[idx] = tl;
}

// attention; consumes kv and q split-K partials + biases directly
__global__ void attn_kernel(const float* __restrict__ qp,
                            const float* __restrict__ kvp,
                            const float* __restrict__ attn_in_b,
                            float* __restrict__ ctx)
{
    int b    = blockIdx.x;
    int warp = threadIdx.x >> 5;
    int lane = threadIdx.x & 31;
    const long QP = (long)BB*DD;
    const long KP = (long)SS*BB*2*DD;

    long qo = (long)b * DD + warp * 64;
    float q0 = qp[qo + lane]      + qp[QP + qo + lane]      + attn_in_b[warp*64 + lane];
    float q1 = qp[qo + lane + 32] + qp[QP + qo + lane + 32] + attn_in_b[warp*64 + lane + 32];

    float sc[SS];
    #pragma unroll
    for (int s = 0; s < SS; s++) {
        long ko = (long)(s*BB + b) * 1024 + warp * 64;
        float k0 = kvp[ko + lane]      + kvp[KP + ko + lane]
                 + attn_in_b[512 + warp*64 + lane];
        float k1 = kvp[ko + lane + 32] + kvp[KP + ko + lane + 32]
                 + attn_in_b[512 + warp*64 + lane + 32];
        float d = q0 * k0 + q1 * k1;
        #pragma unroll
        for (int o = 16; o > 0; o >>= 1) d += __shfl_xor_sync(0xffffffff, d, o);
        sc[s] = d * 0.125f;
    }
    float m = fmaxf(sc[0], fmaxf(sc[1], sc[2]));
    float e[SS], sum = 0.0f;
    #pragma unroll
    for (int s = 0; s < SS; s++) { e[s] = expf(sc[s] - m); sum += e[s]; }
    float inv = 1.0f / sum;

    float c0 = 0.0f, c1 = 0.0f;
    #pragma unroll
    for (int s = 0; s < SS; s++) {
        long vo = (long)(s*BB + b) * 1024 + 512 + warp * 64;
        float v0 = kvp[vo + lane]      + kvp[KP + vo + lane]
                 + attn_in_b[1024 + warp*64 + lane];
        float v1 = kvp[vo + lane + 32] + kvp[KP + vo + lane + 32]
                 + attn_in_b[1024 + warp*64 + lane + 32];
        float w = e[s] * inv;
        c0 += w * v0;
        c1 += w * v1;
    }
    ctx[(long)b * DD + warp*64 + lane]      = c0;
    ctx[(long)b * DD + warp*64 + lane + 32] = c1;
}

// sum 10 proj partial planes + pvec -> layernorm -> out
__global__ void proj_ln_kernel(const float* __restrict__ part,
                               const float* __restrict__ pvec,
                               const float* __restrict__ g,
                               const float* __restrict__ be,
                               float* __restrict__ out)
{
    __shared__ float red[256];
    int row = blockIdx.x, t = threadIdx.x;
    long o0 = (long)row*DD + t, o1 = o0 + 256;
    const long PL = (long)BB*DD;
    float x0 = pvec[t], x1 = pvec[t+256];
    #pragma unroll
    for (int p = 0; p < 10; p++) { x0 += part[p*PL + o0]; x1 += part[p*PL + o1]; }

    red[t] = x0 + x1; __syncthreads();
    for (int o = 128; o > 0; o >>= 1) { if (t < o) red[t] += red[t+o]; __syncthreads(); }
    float mean = red[0] * (1.0f/DD);
    __syncthreads();

    float d0 = x0 - mean, d1 = x1 - mean;
    red[t] = d0*d0 + d1*d1; __syncthreads();
    for (int o = 128; o > 0; o >>= 1) { if (t < o) red[t] += red[t+o]; __syncthreads(); }
    float inv = rsqrtf(red[0] * (1.0f/DD) + 1e-5f);

    out[o0] = d0 * inv * g[t]     + be[t];
    out[o1] = d1 * inv * g[t+256] + be[t+256];
}

// ---------------------------------------------------------------------------
static inline GTask mk_task(const float* X, int ldX, const float* W, int ldW,
                            float* C, int ldC, int K, int kofs,
                            int mtiles, int ntiles)
{
    GTask t = {};
    t.X = X; t.ldX = ldX; t.W = W; t.ldW = ldW; t.C = C; t.ldC = ldC;
    t.K = K; t.kofs = kofs; t.nsplit = NOSPLIT;
    t.mtiles = mtiles; t.blocks = mtiles*ntiles;
    return t;
}

extern "C" void kernel_launch(void* const* d_in, const int* in_sizes, int n_in,
                              void* d_out, int out_size)
{
    (void)in_sizes; (void)n_in; (void)out_size;

    const float* x        = (const float*)d_in[0];
    const float* h_prev   = (const float*)d_in[1];
    const float* lstm_h   = (const float*)d_in[2];
    const float* lstm_c   = (const float*)d_in[3];
    const float* A        = (const float*)d_in[4];
    const float* Bm       = (const float*)d_in[5];
    const float* dn_w1    = (const float*)d_in[6];
    const float* dn_b1    = (const float*)d_in[7];
    const float* dn_g     = (const float*)d_in[8];
    const float* dn_beta  = (const float*)d_in[9];
    const float* dn_w2    = (const float*)d_in[10];
    const float* dn_b2    = (const float*)d_in[11];
    const float* lstm_wih = (const float*)d_in[12];
    const float* lstm_whh = (const float*)d_in[13];
    const float* lstm_bih = (const float*)d_in[14];
    const float* lstm_bhh = (const float*)d_in[15];
    const float* decays   = (const float*)d_in[16];
    const float* attn_in_w  = (const float*)d_in[17];
    const float* attn_in_b  = (const float*)d_in[18];
    const float* attn_out_w = (const float*)d_in[19];
    const float* attn_out_b = (const float*)d_in[20];
    const float* proj_w   = (const float*)d_in[21];
    const float* proj_b   = (const float*)d_in[22];
    const float* proj_g   = (const float*)d_in[23];
    const float* proj_beta= (const float*)d_in[24];

    float* out = (float*)d_out;
    float* out_y    = out;
    float* out_hssm = out + BB*DD;
    float* out_hnew = out + 2*BB*DD;
    float* out_cnew = out + 2*BB*DD + SS*BB*DD;

    float *p_h1, *p_delta, *p_bx, *p_T, *p_U, *p_AT, *p_A2T, *p_A4T, *p_AoT,
          *p_M, *p_Wpow, *p_gA, *p_gB, *p_kvp, *p_qp, *p_ctx, *p_part, *p_pvec;
    cudaGetSymbolAddress((void**)&p_h1,    g_h1);
    cudaGetSymbolAddress((void**)&p_delta, g_delta);
    cudaGetSymbolAddress((void**)&p_bx,    g_bx);
    cudaGetSymbolAddress((void**)&p_T,     g_T);
    cudaGetSymbolAddress((void**)&p_U,     g_U);
    cudaGetSymbolAddress((void**)&p_AT,    g_AT);
    cudaGetSymbolAddress((void**)&p_A2T,   g_A2T);
    cudaGetSymbolAddress((void**)&p_A4T,   g_A4T);
    cudaGetSymbolAddress((void**)&p_AoT,   g_AoT);
    cudaGetSymbolAddress((void**)&p_M,     g_M);
    cudaGetSymbolAddress((void**)&p_Wpow,  g_Wpow);
    cudaGetSymbolAddress((void**)&p_gA,    g_gA);
    cudaGetSymbolAddress((void**)&p_gB,    g_gB);
    cudaGetSymbolAddress((void**)&p_kvp,   g_kvp);
    cudaGetSymbolAddress((void**)&p_qp,    g_qp);
    cudaGetSymbolAddress((void**)&p_ctx,   g_ctx);
    cudaGetSymbolAddress((void**)&p_part,  g_part);
    cudaGetSymbolAddress((void**)&p_pvec,  g_pvec);

    const long W2 = (long)DD*DD;
    const long KP = (long)SS*BB*2*DD;

    // ---- T0: AT = A^T (+Wpow0 = A), AoT = attn_out_w^T ----
    transpose2_kernel<<<dim3(16,16,2), dim3(32,8)>>>(A, p_AT, p_Wpow,
                                                     attn_out_w, p_AoT);

    // ---- G1 (480 blocks): h1|bx, 6 lstm partials, A^2 (+A2T), M ----
    {
        GTaskSet ts = {};
        GTask t0 = mk_task(x, DD, dn_w1, DD, p_h1, DD, DD, 0, 2, 16);
        t0.bias = dn_b1; t0.Wn2 = Bm; t0.Cn2 = p_bx; t0.ldCn2 = DD; t0.nsplit = DD;
        ts.t[0] = t0;
        for (int s = 0; s < SS; s++) {
            ts.t[1+s] = mk_task(x, DD, lstm_wih + (long)s*4*W2, DD,
                                p_gA + (long)s*BB*4*DD, 4*DD, DD, 0, 2, 32);
            ts.t[4+s] = mk_task(lstm_h + (long)s*BB*DD, DD,
                                lstm_whh + (long)s*4*W2, DD,
                                p_gB + (long)s*BB*4*DD, 4*DD, DD, 0, 2, 32);
        }
        GTask ta = mk_task(A, DD, p_AT, DD, p_Wpow + W2, DD, DD, 0, 4, 8);
        ta.Ct = p_A2T; ta.ldCt = DD;
        ts.t[7] = ta;
        ts.t[8] = mk_task(proj_w + 512, 5*DD, p_AoT, DD, p_M, DD, DD, 0, 4, 8);
        ts.ntasks = 9;
        gemm_mma<<<480, 256>>>(ts);
    }

    // ---- S1 fused: delta, pvec, lstm pointwise ----
    s1_kernel<<<2304, 256>>>(p_h1, dn_g, dn_beta, dn_w2, dn_b2, p_delta,
                             proj_w, attn_out_b, proj_b, p_pvec,
                             p_gA, p_gB, lstm_bih, lstm_bhh, lstm_c, decays,
                             out_hnew, out_cnew);

    // ---- G2 (256 blocks): A^3, A^4 (+A4T), kv split-K-2 ----
    {
        GTaskSet ts = {};
        ts.t[0] = mk_task(p_Wpow + W2, DD, p_AT, DD, p_Wpow + 2*W2, DD, DD, 0, 4, 8);
        GTask t4 = mk_task(p_Wpow + W2, DD, p_A2T, DD, p_Wpow + 3*W2, DD, DD, 0, 4, 8);
        t4.Ct = p_A4T; t4.ldCt = DD;
        ts.t[1] = t4;
        for (int kz = 0; kz < 2; kz++)
            ts.t[2+kz] = mk_task(out_hnew, DD, attn_in_w + W2, DD,
                                 p_kvp + (long)kz*KP, 2*DD, 256, kz*256, 6, 16);
        ts.ntasks = 4;
        gemm_mma<<<256, 256>>>(ts);
    }

    // ---- G3 (224 blocks): A^5..A^8, h_new proj partials (planes 4..9) ----
    {
        GTaskSet ts = {};
        ts.t[0] = mk_task(p_Wpow + 3*W2, DD, p_AT,  DD, p_Wpow + 4*W2, DD, DD, 0, 4, 8);
        ts.t[1] = mk_task(p_Wpow + 3*W2, DD, p_A2T, DD, p_Wpow + 5*W2, DD, DD, 0, 4, 8);
        ts.t[2] = mk_task(p_Wpow + 2*W2, DD, p_A4T, DD, p_Wpow + 6*W2, DD, DD, 0, 4, 8);
        ts.t[3] = mk_task(p_Wpow + 3*W2, DD, p_A4T, DD, p_Wpow + 7*W2, DD, DD, 0, 4, 8);
        int p = 0;
        for (int i = 0; i < SS; i++)
            for (int kz = 0; kz < 2; kz++, p++)
                ts.t[4+p] = mk_task(out_hnew + (long)i*BB*DD, DD,
                                    proj_w + 1024 + i*512, 5*DD,
                                    p_part + (long)(4 + p)*BB*DD, DD,
                                    256, kz*256, 2, 8);
        ts.ntasks = 10;
        gemm_mma<<<224, 256>>>(ts);
    }

    // ---- chain: 2 iters x 8 terms (KT=16), no split-K (N=4096) ----
    {
        GTaskSet ts = {};
        ts.t[0] = mk_task(h_prev, DD, p_Wpow, DD, p_U, 8*DD, DD, 0, 2, 64);
        ts.ntasks = 1;
        gemm_mma<<<128, 256>>>(ts);
    }
    chain_epilogue_kernel<<<(BB*DD)/256, 256>>>(
        p_U, p_delta, p_T, out_hssm, h_prev, 0, 8, p_bx, 0);
    {
        GTaskSet ts = {};
        ts.t[0] = mk_task(p_T, DD, p_Wpow, DD, p_U, 8*DD, DD, 0, 2, 64);
        ts.ntasks = 1;
        gemm_mma<<<128, 256>>>(ts);
    }
    chain_epilogue_kernel<<<(BB*DD)/256, 256>>>(
        p_U, p_delta, p_T, out_hssm, h_prev, 8, 8, p_bx, 1);

    // ---- G4 (64 blocks): q split-K-2 + hssm proj (planes 0,1) ----
    {
        GTaskSet ts = {};
        for (int kz = 0; kz < 2; kz++) {
            ts.t[kz] = mk_task(out_hssm, DD, attn_in_w, DD,
                               p_qp + (long)kz*BB*DD, DD, 256, kz*256, 2, 8);
            ts.t[2+kz] = mk_task(out_hssm, DD, proj_w, 5*DD,
                                 p_part + (long)kz*BB*DD, DD, 256, kz*256, 2, 8);
        }
        ts.ntasks = 4;
        gemm_mma<<<64, 256>>>(ts);
    }

    // ---- attention (consumes partials + bias) ----
    attn_kernel<<<BB, 256>>>(p_qp, p_kvp, attn_in_b, p_ctx);

    // ---- G5 (32 blocks): ctx @ M^T -> planes 2,3 ----
    {
        GTaskSet ts = {};
        for (int kz = 0; kz < 2; kz++)
            ts.t[kz] = mk_task(p_ctx, DD, p_M, DD,
                               p_part + (long)(2+kz)*BB*DD, DD, 256, kz*256, 2, 8);
        ts.ntasks = 2;
        gemm_mma<<<32, 256>>>(ts);
    }

    // ---- reduce + LN -> out_y ----
    proj_ln_kernel<<<BB, 256>>>(p_part, p_pvec, proj_g, proj_beta, out_y);
}

// round 9
// speedup vs baseline: 1.1995x; 1.0326x over previous
#include <cuda_runtime.h>
#include <cuda_bf16.h>
#include <math.h>
#include <cstdint>

// ---------------------------------------------------------------------------
// SSMXLSTMFusion: D=512, S=3, BATCH=256, H=8, HD=64
// Round 9: double-buffered smem pipeline (1 sync/chunk, STS/LDG overlap MMA).
// 128x64 tiles, 2 CTAs/SM, Taylor chain 2x8 terms (A^1..A^8, KT=16),
// bf16 hi/lo emulated fp32 mma.sync.
// ---------------------------------------------------------------------------

#define DD    512
#define BB    256
#define SS    3

// ------------------------- scratch (device globals) ------------------------
__device__ float g_h1   [BB*DD];
__device__ float g_delta[BB];
__device__ float g_bx   [BB*DD];
__device__ float g_T    [BB*DD];
__device__ float g_U    [BB*8*DD];
__device__ float g_AT   [DD*DD];
__device__ float g_A2T  [DD*DD];
__device__ float g_A4T  [DD*DD];
__device__ float g_AoT  [DD*DD];
__device__ float g_M    [DD*DD];
__device__ float g_Wpow [8*DD*DD];
__device__ float g_gA   [SS*BB*4*DD];
__device__ float g_gB   [SS*BB*4*DD];
__device__ float g_kvp  [2*SS*BB*2*DD];
__device__ float g_qp   [2*BB*DD];
__device__ float g_ctx  [BB*DD];
__device__ float g_part [10*BB*DD];
__device__ float g_pvec [DD];

// ========================= task descriptor ==================================
struct GTask {
    const float *X, *W, *Wn2, *bias;
    float *C, *Cn2, *Ct;
    int ldX, ldW, ldC, ldCn2, ldCt;
    int K, kofs, nsplit, mtiles, blocks;
};
struct GTaskSet { GTask t[12]; int ntasks; };

#define NOSPLIT (1<<30)

// ========================= smem layout ======================================
#define RSB     80
#define OFF_AHI 0
#define OFF_ALO 10240
#define OFF_BHI 20480
#define OFF_BLO 25600
#define STAGE   30720
#define SMEM_SZ (2*STAGE)     // 61440 bytes, dynamic

__device__ __forceinline__ uint32_t smem_to_u32(const void* p) {
    uint32_t a;
    asm("{ .reg .u64 t; cvta.to.shared.u64 t, %1; cvt.u32.u64 %0, t; }"
        : "=r"(a) : "l"(p));
    return a;
}

__device__ __forceinline__ uint32_t pkbf(float a, float b) {
    __nv_bfloat16 h0 = __float2bfloat16_rn(a);
    __nv_bfloat16 h1 = __float2bfloat16_rn(b);
    uint16_t u0 = *(uint16_t*)&h0, u1 = *(uint16_t*)&h1;
    return (uint32_t)u0 | ((uint32_t)u1 << 16);
}

__device__ __forceinline__ void split8(float4 u, float4 v, uint4& hi, uint4& lo)
{
    float f[8] = {u.x,u.y,u.z,u.w,v.x,v.y,v.z,v.w};
    float r[8];
    uint32_t h[4];
    #pragma unroll
    for (int i = 0; i < 4; i++) {
        __nv_bfloat16 b0 = __float2bfloat16_rn(f[2*i]);
        __nv_bfloat16 b1 = __float2bfloat16_rn(f[2*i+1]);
        r[2*i]   = f[2*i]   - __bfloat162float(b0);
        r[2*i+1] = f[2*i+1] - __bfloat162float(b1);
        uint16_t u0 = *(uint16_t*)&b0, u1 = *(uint16_t*)&b1;
        h[i] = (uint32_t)u0 | ((uint32_t)u1 << 16);
    }
    hi = make_uint4(h[0], h[1], h[2], h[3]);
    lo = make_uint4(pkbf(r[0],r[1]), pkbf(r[2],r[3]),
                    pkbf(r[4],r[5]), pkbf(r[6],r[7]));
}

__device__ __forceinline__ void ldm_x4(uint32_t* r, uint32_t addr) {
    asm volatile("ldmatrix.sync.aligned.m8n8.x4.shared.b16 {%0,%1,%2,%3}, [%4];"
        : "=r"(r[0]), "=r"(r[1]), "=r"(r[2]), "=r"(r[3]) : "r"(addr));
}

__device__ __forceinline__ void mma_bf16(float* c, const uint32_t* a, const uint32_t* b)
{
    asm volatile(
        "mma.sync.aligned.m16n8k16.row.col.f32.bf16.bf16.f32 "
        "{%0,%1,%2,%3}, {%4,%5,%6,%7}, {%8,%9}, {%0,%1,%2,%3};"
        : "+f"(c[0]), "+f"(c[1]), "+f"(c[2]), "+f"(c[3])
        : "r"(a[0]), "r"(a[1]), "r"(a[2]), "r"(a[3]), "r"(b[0]), "r"(b[1]));
}

__device__ __forceinline__ void do_prefetch(const GTask& T, int m0, int n0,
    int rowA, int rB, int sl, int k0, float4* pfA, float4* pfB)
{
    const float* a0 = T.X + (long)(m0 + rowA) * T.ldX + k0 + sl*8;
    pfA[0] = ((const float4*)a0)[0]; pfA[1] = ((const float4*)a0)[1];
    const float* a1 = a0 + (long)64 * T.ldX;
    pfA[2] = ((const float4*)a1)[0]; pfA[3] = ((const float4*)a1)[1];
    int ng = n0 + rB;
    const float* br = (ng >= T.nsplit)
        ? T.Wn2 + (long)(ng - T.nsplit) * T.ldW
        : T.W   + (long)ng * T.ldW;
    const float* b0 = br + k0 + sl*8;
    pfB[0] = ((const float4*)b0)[0]; pfB[1] = ((const float4*)b0)[1];
}

__device__ __forceinline__ void do_sts(char* smem, int sbase,
    int rowA, int rB, int sl, const float4* pfA, const float4* pfB)
{
    char* phA = smem + sbase + OFF_AHI + rowA * RSB + sl * 16;
    char* plA = smem + sbase + OFF_ALO + rowA * RSB + sl * 16;
    uint4 hi, lo;
    split8(pfA[0], pfA[1], hi, lo);
    *(uint4*)(phA) = hi; *(uint4*)(plA) = lo;
    split8(pfA[2], pfA[3], hi, lo);
    *(uint4*)(phA + 64*RSB) = hi; *(uint4*)(plA + 64*RSB) = lo;
    split8(pfB[0], pfB[1], hi, lo);
    *(uint4*)(smem + sbase + OFF_BHI + rB * RSB + sl * 16) = hi;
    *(uint4*)(smem + sbase + OFF_BLO + rB * RSB + sl * 16) = lo;
}

// ========================= GEMM kernel ======================================
// Block tile 128(M) x 64(N); 256 threads, warp tile 32x32; double-buffered
// K chunks of 32 with one __syncthreads per chunk. 2 CTAs per SM.
__global__ void __launch_bounds__(256, 2)
gemm_mma(GTaskSet ts)
{
    extern __shared__ char smem[];

    int b = blockIdx.x, ti = 0;
    while (b >= ts.t[ti].blocks) { b -= ts.t[ti].blocks; ti++; }
    const GTask T = ts.t[ti];
    const int m0 = (b % T.mtiles) * 128;
    const int n0 = (b / T.mtiles) * 64;

    const int tid = threadIdx.x;
    const int lid = tid & 31;
    const int wid = tid >> 5;
    const int m_base = (wid & 3) * 32;
    const int n_base = (wid >> 2) * 32;
    const int gid = lid >> 2;
    const int tig = lid & 3;
    const int g  = lid >> 3;
    const int ig = lid & 7;

    const uint32_t sm = smem_to_u32(smem);
    const uint32_t a_ad = sm + (uint32_t)((m_base + (g&1)*8 + ig) * RSB + (g>>1)*16);
    const uint32_t b_ad = sm + (uint32_t)((n_base + (g>>1)*8 + ig) * RSB + (g&1)*16);

    float acc[2][4][4];
    #pragma unroll
    for (int i = 0; i < 2; i++)
        #pragma unroll
        for (int j = 0; j < 4; j++)
            #pragma unroll
            for (int k = 0; k < 4; k++) acc[i][j][k] = 0.0f;

    const int rowA = tid >> 2;          // 0..63 -> rows rowA, rowA+64
    const int sl   = tid & 3;
    const int rB   = (tid >> 2) & 63;

    const int nc = T.K >> 5;
    float4 pfA[4], pfB[2];

    // prologue: chunk0 -> buf0; prefetch chunk1
    do_prefetch(T, m0, n0, rowA, rB, sl, T.kofs, pfA, pfB);
    do_sts(smem, 0, rowA, rB, sl, pfA, pfB);
    if (nc > 1)
        do_prefetch(T, m0, n0, rowA, rB, sl, T.kofs + 32, pfA, pfB);
    __syncthreads();

    for (int c = 0; c < nc; c++) {
        const int stage = c & 1;
        const uint32_t sb = (uint32_t)(stage * STAGE);

        // stage chunk c+1 into the other buffer; prefetch chunk c+2
        if (c + 1 < nc) {
            do_sts(smem, (1 - stage) * STAGE, rowA, rB, sl, pfA, pfB);
            if (c + 2 < nc)
                do_prefetch(T, m0, n0, rowA, rB, sl, T.kofs + (c+2)*32, pfA, pfB);
        }

        // ---- MMA on buf[stage]: 2 k-steps of 16 ----
        #pragma unroll
        for (int ks = 0; ks < 2; ks++) {
            const uint32_t kb = sb + ks * 32;
            uint32_t ahi[2][4], alo[2][4], bhi[4][2], blo[4][2];
            #pragma unroll
            for (int mt = 0; mt < 2; mt++) {
                ldm_x4(ahi[mt], a_ad + OFF_AHI + mt*16*RSB + kb);
                ldm_x4(alo[mt], a_ad + OFF_ALO + mt*16*RSB + kb);
            }
            #pragma unroll
            for (int np = 0; np < 2; np++) {
                uint32_t r[4];
                ldm_x4(r, b_ad + OFF_BHI + np*16*RSB + kb);
                bhi[2*np][0] = r[0]; bhi[2*np][1] = r[1];
                bhi[2*np+1][0] = r[2]; bhi[2*np+1][1] = r[3];
                ldm_x4(r, b_ad + OFF_BLO + np*16*RSB + kb);
                blo[2*np][0] = r[0]; blo[2*np][1] = r[1];
                blo[2*np+1][0] = r[2]; blo[2*np+1][1] = r[3];
            }
            #pragma unroll
            for (int mt = 0; mt < 2; mt++)
                #pragma unroll
                for (int nt = 0; nt < 4; nt++) {
                    mma_bf16(acc[mt][nt], ahi[mt], bhi[nt]);
                    mma_bf16(acc[mt][nt], ahi[mt], blo[nt]);
                    mma_bf16(acc[mt][nt], alo[mt], bhi[nt]);
                }
        }
        __syncthreads();
    }

    #pragma unroll
    for (int mt = 0; mt < 2; mt++) {
        #pragma unroll
        for (int nt = 0; nt < 4; nt++) {
            int n = n0 + n_base + nt*8 + tig*2;
            #pragma unroll
            for (int half = 0; half < 2; half++) {
                int mm = m0 + m_base + mt*16 + gid + half*8;
                float v0 = acc[mt][nt][half*2];
                float v1 = acc[mt][nt][half*2 + 1];
                if (T.Cn2 && n >= T.nsplit) {
                    int nn = n - T.nsplit;
                    *(float2*)(T.Cn2 + (long)mm*T.ldCn2 + nn) = make_float2(v0, v1);
                } else {
                    if (T.bias) { v0 += T.bias[n]; v1 += T.bias[n+1]; }
                    *(float2*)(T.C + (long)mm*T.ldC + n) = make_float2(v0, v1);
                    if (T.Ct) {
                        T.Ct[(long)n*T.ldCt + mm]     = v0;
                        T.Ct[(long)(n+1)*T.ldCt + mm] = v1;
                    }
                }
            }
        }
    }
}

// ========================= small SIMT kernels ===============================
__global__ void transpose2_kernel(const float* __restrict__ A,
                                  float* __restrict__ AT,
                                  float* __restrict__ W0,
                                  const float* __restrict__ B,
                                  float* __restrict__ BT)
{
    __shared__ float t[32][33];
    const float* src = blockIdx.z ? B : A;
    float* dst = blockIdx.z ? BT : AT;
    int bx = blockIdx.x*32, by = blockIdx.y*32;
    int x = bx + threadIdx.x;
    #pragma unroll
    for (int i = 0; i < 32; i += 8) {
        int y = by + threadIdx.y + i;
        float v = src[(long)y*DD + x];
        t[threadIdx.y + i][threadIdx.x] = v;
        if (blockIdx.z == 0) W0[(long)y*DD + x] = v;
    }
    __syncthreads();
    int xo = by + threadIdx.x;
    #pragma unroll
    for (int i = 0; i < 32; i += 8) {
        int yo = bx + threadIdx.y + i;
        dst[(long)yo*DD + xo] = t[threadIdx.x][threadIdx.y + i];
    }
}

__device__ __forceinline__ float sigf(float x) { return 1.0f / (1.0f + expf(-x)); }

// fused S1: blocks [0,256) delta; [256,768) pvec; [768,2304) lstm pointwise
__global__ void s1_kernel(const float* __restrict__ h1,
                          const float* __restrict__ dn_g,
                          const float* __restrict__ dn_beta,
                          const float* __restrict__ w2,
                          const float* __restrict__ b2,
                          float* __restrict__ delta,
                          const float* __restrict__ proj_w,
                          const float* __restrict__ aob,
                          const float* __restrict__ proj_b,
                          float* __restrict__ pvec,
                          const float* __restrict__ gA,
                          const float* __restrict__ gB,
                          const float* __restrict__ bih,
                          const float* __restrict__ bhh,
                          const float* __restrict__ lstm_c,
                          const float* __restrict__ decays,
                          float* __restrict__ h_new,
                          float* __restrict__ c_new)
{
    int blk = blockIdx.x, t = threadIdx.x;
    if (blk < 256) {
        __shared__ float red[256];
        int row = blk;
        const float* r = h1 + (long)row * DD;
        float x0 = r[t], x1 = r[t + 256];
        red[t] = x0 + x1; __syncthreads();
        for (int o = 128; o > 0; o >>= 1) { if (t < o) red[t] += red[t+o]; __syncthreads(); }
        float mean = red[0] * (1.0f/DD);
        __syncthreads();
        float d0 = x0 - mean, d1 = x1 - mean;
        red[t] = d0*d0 + d1*d1; __syncthreads();
        for (int o = 128; o > 0; o >>= 1) { if (t < o) red[t] += red[t+o]; __syncthreads(); }
        float inv = rsqrtf(red[0] * (1.0f/DD) + 1e-5f);
        __syncthreads();
        float y0 = d0 * inv * dn_g[t]     + dn_beta[t];
        float y1 = d1 * inv * dn_g[t+256] + dn_beta[t+256];
        y0 = 0.5f * y0 * (1.0f + erff(y0 * 0.70710678118654752f));
        y1 = 0.5f * y1 * (1.0f + erff(y1 * 0.70710678118654752f));
        red[t] = y0*w2[t] + y1*w2[t+256]; __syncthreads();
        for (int o = 128; o > 0; o >>= 1) { if (t < o) red[t] += red[t+o]; __syncthreads(); }
        if (t == 0) {
            float z = red[0] + b2[0];
            delta[row] = (z > 20.0f) ? z : log1pf(expf(z));
        }
    } else if (blk < 768) {
        __shared__ float red[256];
        int row = blk - 256;
        const float* r = proj_w + (long)row * 2560 + 512;
        red[t] = r[t]*aob[t] + r[t+256]*aob[t+256];
        __syncthreads();
        for (int o = 128; o > 0; o >>= 1) { if (t < o) red[t] += red[t+o]; __syncthreads(); }
        if (t == 0) pvec[row] = proj_b[row] + red[0];
    } else {
        int idx = (blk - 768) * 256 + t;
        int s = idx / (BB*DD);
        int r = idx - s * (BB*DD);
        int b = r >> 9;
        int d = r & 511;
        long gbase = ((long)s * BB + b) * 2048;
        const float* a = gA + gbase;
        const float* h = gB + gbase;
        const float* bi = bih + s*2048;
        const float* bh = bhh + s*2048;
        float ip = a[d]      + h[d]      + bi[d]      + bh[d];
        float fp = a[512+d]  + h[512+d]  + bi[512+d]  + bh[512+d];
        float gp = a[1024+d] + h[1024+d] + bi[1024+d] + bh[1024+d];
        float op = a[1536+d] + h[1536+d] + bi[1536+d] + bh[1536+d];
        float i_g = sigf(ip);
        float f_g = sigf(fp);
        float g_g = tanhf(gp);
        float o_g = sigf(op);
        float c   = lstm_c[idx];
        float craw = f_g * c + i_g * g_g;
        float hn   = o_g * tanhf(craw);
        float dec  = decays[s];
        h_new[idx] = hn;
        c_new[idx] = dec * c + (1.0f - dec) * craw;
    }
}

// chain epilogue: U single plane [256, nt*512]
__global__ void chain_epilogue_kernel(const float* __restrict__ U,
                                      const float* __restrict__ delta,
                                      float* __restrict__ T,
                                      float* __restrict__ y,
                                      const float* __restrict__ h_prev,
                                      int k0, int nt,
                                      const float* __restrict__ bx,
                                      int last)
{
    int idx = blockIdx.x * blockDim.x + threadIdx.x;
    if (idx >= BB*DD) return;
    int b = idx >> 9, n = idx & 511;
    const float* u0 = U + (long)b * (nt*512) + n;
    float d  = delta[b];
    float c  = 1.0f;
    float yy = (k0 == 0) ? h_prev[idx] : y[idx];
    float tl = 0.0f;
    for (int j = 0; j < nt; j++) {
        float u = u0[j*512];
        c *= d / (float)(k0 + j + 1);
        tl = c * u;
        yy += tl;
    }
    if (last) yy += d * bx[idx];
    y[idx] = yy;
    T[idx] = tl;
}

// attention; consumes kv and q split-K partials + biases directly
__global__ void attn_kernel(const float* __restrict__ qp,
                            const float* __restrict__ kvp,
                            const float* __restrict__ attn_in_b,
                            float* __restrict__ ctx)
{
    int b    = blockIdx.x;
    int warp = threadIdx.x >> 5;
    int lane = threadIdx.x & 31;
    const long QP = (long)BB*DD;
    const long KP = (long)SS*BB*2*DD;

    long qo = (long)b * DD + warp * 64;
    float q0 = qp[qo + lane]      + qp[QP + qo + lane]      + attn_in_b[warp*64 + lane];
    float q1 = qp[qo + lane + 32] + qp[QP + qo + lane + 32] + attn_in_b[warp*64 + lane + 32];

    float sc[SS];
    #pragma unroll
    for (int s = 0; s < SS; s++) {
        long ko = (long)(s*BB + b) * 1024 + warp * 64;
        float k0 = kvp[ko + lane]      + kvp[KP + ko + lane]
                 + attn_in_b[512 + warp*64 + lane];
        float k1 = kvp[ko + lane + 32] + kvp[KP + ko + lane + 32]
                 + attn_in_b[512 + warp*64 + lane + 32];
        float d = q0 * k0 + q1 * k1;
        #pragma unroll
        for (int o = 16; o > 0; o >>= 1) d += __shfl_xor_sync(0xffffffff, d, o);
        sc[s] = d * 0.125f;
    }
    float m = fmaxf(sc[0], fmaxf(sc[1], sc[2]));
    float e[SS], sum = 0.0f;
    #pragma unroll
    for (int s = 0; s < SS; s++) { e[s] = expf(sc[s] - m); sum += e[s]; }
    float inv = 1.0f / sum;

    float c0 = 0.0f, c1 = 0.0f;
    #pragma unroll
    for (int s = 0; s < SS; s++) {
        long vo = (long)(s*BB + b) * 1024 + 512 + warp * 64;
        float v0 = kvp[vo + lane]      + kvp[KP + vo + lane]
                 + attn_in_b[1024 + warp*64 + lane];
        float v1 = kvp[vo + lane + 32] + kvp[KP + vo + lane + 32]
                 + attn_in_b[1024 + warp*64 + lane + 32];
        float w = e[s] * inv;
        c0 += w * v0;
        c1 += w * v1;
    }
    ctx[(long)b * DD + warp*64 + lane]      = c0;
    ctx[(long)b * DD + warp*64 + lane + 32] = c1;
}

// sum 10 proj partial planes + pvec -> layernorm -> out
__global__ void proj_ln_kernel(const float* __restrict__ part,
                               const float* __restrict__ pvec,
                               const float* __restrict__ g,
                               const float* __restrict__ be,
                               float* __restrict__ out)
{
    __shared__ float red[256];
    int row = blockIdx.x, t = threadIdx.x;
    long o0 = (long)row*DD + t, o1 = o0 + 256;
    const long PL = (long)BB*DD;
    float x0 = pvec[t], x1 = pvec[t+256];
    #pragma unroll
    for (int p = 0; p < 10; p++) { x0 += part[p*PL + o0]; x1 += part[p*PL + o1]; }

    red[t] = x0 + x1; __syncthreads();
    for (int o = 128; o > 0; o >>= 1) { if (t < o) red[t] += red[t+o]; __syncthreads(); }
    float mean = red[0] * (1.0f/DD);
    __syncthreads();

    float d0 = x0 - mean, d1 = x1 - mean;
    red[t] = d0*d0 + d1*d1; __syncthreads();
    for (int o = 128; o > 0; o >>= 1) { if (t < o) red[t] += red[t+o]; __syncthreads(); }
    float inv = rsqrtf(red[0] * (1.0f/DD) + 1e-5f);

    out[o0] = d0 * inv * g[t]     + be[t];
    out[o1] = d1 * inv * g[t+256] + be[t+256];
}

// ---------------------------------------------------------------------------
static inline GTask mk_task(const float* X, int ldX, const float* W, int ldW,
                            float* C, int ldC, int K, int kofs,
                            int mtiles, int ntiles)
{
    GTask t = {};
    t.X = X; t.ldX = ldX; t.W = W; t.ldW = ldW; t.C = C; t.ldC = ldC;
    t.K = K; t.kofs = kofs; t.nsplit = NOSPLIT;
    t.mtiles = mtiles; t.blocks = mtiles*ntiles;
    return t;
}

extern "C" void kernel_launch(void* const* d_in, const int* in_sizes, int n_in,
                              void* d_out, int out_size)
{
    (void)in_sizes; (void)n_in; (void)out_size;

    const float* x        = (const float*)d_in[0];
    const float* h_prev   = (const float*)d_in[1];
    const float* lstm_h   = (const float*)d_in[2];
    const float* lstm_c   = (const float*)d_in[3];
    const float* A        = (const float*)d_in[4];
    const float* Bm       = (const float*)d_in[5];
    const float* dn_w1    = (const float*)d_in[6];
    const float* dn_b1    = (const float*)d_in[7];
    const float* dn_g     = (const float*)d_in[8];
    const float* dn_beta  = (const float*)d_in[9];
    const float* dn_w2    = (const float*)d_in[10];
    const float* dn_b2    = (const float*)d_in[11];
    const float* lstm_wih = (const float*)d_in[12];
    const float* lstm_whh = (const float*)d_in[13];
    const float* lstm_bih = (const float*)d_in[14];
    const float* lstm_bhh = (const float*)d_in[15];
    const float* decays   = (const float*)d_in[16];
    const float* attn_in_w  = (const float*)d_in[17];
    const float* attn_in_b  = (const float*)d_in[18];
    const float* attn_out_w = (const float*)d_in[19];
    const float* attn_out_b = (const float*)d_in[20];
    const float* proj_w   = (const float*)d_in[21];
    const float* proj_b   = (const float*)d_in[22];
    const float* proj_g   = (const float*)d_in[23];
    const float* proj_beta= (const float*)d_in[24];

    float* out = (float*)d_out;
    float* out_y    = out;
    float* out_hssm = out + BB*DD;
    float* out_hnew = out + 2*BB*DD;
    float* out_cnew = out + 2*BB*DD + SS*BB*DD;

    float *p_h1, *p_delta, *p_bx, *p_T, *p_U, *p_AT, *p_A2T, *p_A4T, *p_AoT,
          *p_M, *p_Wpow, *p_gA, *p_gB, *p_kvp, *p_qp, *p_ctx, *p_part, *p_pvec;
    cudaGetSymbolAddress((void**)&p_h1,    g_h1);
    cudaGetSymbolAddress((void**)&p_delta, g_delta);
    cudaGetSymbolAddress((void**)&p_bx,    g_bx);
    cudaGetSymbolAddress((void**)&p_T,     g_T);
    cudaGetSymbolAddress((void**)&p_U,     g_U);
    cudaGetSymbolAddress((void**)&p_AT,    g_AT);
    cudaGetSymbolAddress((void**)&p_A2T,   g_A2T);
    cudaGetSymbolAddress((void**)&p_A4T,   g_A4T);
    cudaGetSymbolAddress((void**)&p_AoT,   g_AoT);
    cudaGetSymbolAddress((void**)&p_M,     g_M);
    cudaGetSymbolAddress((void**)&p_Wpow,  g_Wpow);
    cudaGetSymbolAddress((void**)&p_gA,    g_gA);
    cudaGetSymbolAddress((void**)&p_gB,    g_gB);
    cudaGetSymbolAddress((void**)&p_kvp,   g_kvp);
    cudaGetSymbolAddress((void**)&p_qp,    g_qp);
    cudaGetSymbolAddress((void**)&p_ctx,   g_ctx);
    cudaGetSymbolAddress((void**)&p_part,  g_part);
    cudaGetSymbolAddress((void**)&p_pvec,  g_pvec);

    cudaFuncSetAttribute(gemm_mma,
        cudaFuncAttributeMaxDynamicSharedMemorySize, SMEM_SZ);

    const long W2 = (long)DD*DD;
    const long KP = (long)SS*BB*2*DD;

    // ---- T0: AT = A^T (+Wpow0 = A), AoT = attn_out_w^T ----
    transpose2_kernel<<<dim3(16,16,2), dim3(32,8)>>>(A, p_AT, p_Wpow,
                                                     attn_out_w, p_AoT);

    // ---- G1 (480 blocks): h1|bx, 6 lstm partials, A^2 (+A2T), M ----
    {
        GTaskSet ts = {};
        GTask t0 = mk_task(x, DD, dn_w1, DD, p_h1, DD, DD, 0, 2, 16);
        t0.bias = dn_b1; t0.Wn2 = Bm; t0.Cn2 = p_bx; t0.ldCn2 = DD; t0.nsplit = DD;
        ts.t[0] = t0;
        for (int s = 0; s < SS; s++) {
            ts.t[1+s] = mk_task(x, DD, lstm_wih + (long)s*4*W2, DD,
                                p_gA + (long)s*BB*4*DD, 4*DD, DD, 0, 2, 32);
            ts.t[4+s] = mk_task(lstm_h + (long)s*BB*DD, DD,
                                lstm_whh + (long)s*4*W2, DD,
                                p_gB + (long)s*BB*4*DD, 4*DD, DD, 0, 2, 32);
        }
        GTask ta = mk_task(A, DD, p_AT, DD, p_Wpow + W2, DD, DD, 0, 4, 8);
        ta.Ct = p_A2T; ta.ldCt = DD;
        ts.t[7] = ta;
        ts.t[8] = mk_task(proj_w + 512, 5*DD, p_AoT, DD, p_M, DD, DD, 0, 4, 8);
        ts.ntasks = 9;
        gemm_mma<<<480, 256, SMEM_SZ>>>(ts);
    }

    // ---- S1 fused: delta, pvec, lstm pointwise ----
    s1_kernel<<<2304, 256>>>(p_h1, dn_g, dn_beta, dn_w2, dn_b2, p_delta,
                             proj_w, attn_out_b, proj_b, p_pvec,
                             p_gA, p_gB, lstm_bih, lstm_bhh, lstm_c, decays,
                             out_hnew, out_cnew);

    // ---- G2 (256 blocks): A^3, A^4 (+A4T), kv split-K-2 ----
    {
        GTaskSet ts = {};
        ts.t[0] = mk_task(p_Wpow + W2, DD, p_AT, DD, p_Wpow + 2*W2, DD, DD, 0, 4, 8);
        GTask t4 = mk_task(p_Wpow + W2, DD, p_A2T, DD, p_Wpow + 3*W2, DD, DD, 0, 4, 8);
        t4.Ct = p_A4T; t4.ldCt = DD;
        ts.t[1] = t4;
        for (int kz = 0; kz < 2; kz++)
            ts.t[2+kz] = mk_task(out_hnew, DD, attn_in_w + W2, DD,
                                 p_kvp + (long)kz*KP, 2*DD, 256, kz*256, 6, 16);
        ts.ntasks = 4;
        gemm_mma<<<256, 256, SMEM_SZ>>>(ts);
    }

    // ---- G3 (224 blocks): A^5..A^8, h_new proj partials (planes 4..9) ----
    {
        GTaskSet ts = {};
        ts.t[0] = mk_task(p_Wpow + 3*W2, DD, p_AT,  DD, p_Wpow + 4*W2, DD, DD, 0, 4, 8);
        ts.t[1] = mk_task(p_Wpow + 3*W2, DD, p_A2T, DD, p_Wpow + 5*W2, DD, DD, 0, 4, 8);
        ts.t[2] = mk_task(p_Wpow + 2*W2, DD, p_A4T, DD, p_Wpow + 6*W2, DD, DD, 0, 4, 8);
        ts.t[3] = mk_task(p_Wpow + 3*W2, DD, p_A4T, DD, p_Wpow + 7*W2, DD, DD, 0, 4, 8);
        int p = 0;
        for (int i = 0; i < SS; i++)
            for (int kz = 0; kz < 2; kz++, p++)
                ts.t[4+p] = mk_task(out_hnew + (long)i*BB*DD, DD,
                                    proj_w + 1024 + i*512, 5*DD,
                                    p_part + (long)(4 + p)*BB*DD, DD,
                                    256, kz*256, 2, 8);
        ts.ntasks = 10;
        gemm_mma<<<224, 256, SMEM_SZ>>>(ts);
    }

    // ---- chain: 2 iters x 8 terms (KT=16) ----
    {
        GTaskSet ts = {};
        ts.t[0] = mk_task(h_prev, DD, p_Wpow, DD, p_U, 8*DD, DD, 0, 2, 64);
        ts.ntasks = 1;
        gemm_mma<<<128, 256, SMEM_SZ>>>(ts);
    }
    chain_epilogue_kernel<<<(BB*DD)/256, 256>>>(
        p_U, p_delta, p_T, out_hssm, h_prev, 0, 8, p_bx, 0);
    {
        GTaskSet ts = {};
        ts.t[0] = mk_task(p_T, DD, p_Wpow, DD, p_U, 8*DD, DD, 0, 2, 64);
        ts.ntasks = 1;
        gemm_mma<<<128, 256, SMEM_SZ>>>(ts);
    }
    chain_epilogue_kernel<<<(BB*DD)/256, 256>>>(
        p_U, p_delta, p_T, out_hssm, h_prev, 8, 8, p_bx, 1);

    // ---- G4 (64 blocks): q split-K-2 + hssm proj (planes 0,1) ----
    {
        GTaskSet ts = {};
        for (int kz = 0; kz < 2; kz++) {
            ts.t[kz] = mk_task(out_hssm, DD, attn_in_w, DD,
                               p_qp + (long)kz*BB*DD, DD, 256, kz*256, 2, 8);
            ts.t[2+kz] = mk_task(out_hssm, DD, proj_w, 5*DD,
                                 p_part + (long)kz*BB*DD, DD, 256, kz*256, 2, 8);
        }
        ts.ntasks = 4;
        gemm_mma<<<64, 256, SMEM_SZ>>>(ts);
    }

    // ---- attention (consumes partials + bias) ----
    attn_kernel<<<BB, 256>>>(p_qp, p_kvp, attn_in_b, p_ctx);

    // ---- G5 (32 blocks): ctx @ M^T -> planes 2,3 ----
    {
        GTaskSet ts = {};
        for (int kz = 0; kz < 2; kz++)
            ts.t[kz] = mk_task(p_ctx, DD, p_M, DD,
                               p_part + (long)(2+kz)*BB*DD, DD, 256, kz*256, 2, 8);
        ts.ntasks = 2;
        gemm_mma<<<32, 256, SMEM_SZ>>>(ts);
    }

    // ---- reduce + LN -> out_y ----
    proj_ln_kernel<<<BB, 256>>>(p_part, p_pvec, proj_g, proj_beta, out_y);
}